// round 1
// baseline (speedup 1.0000x reference)
#include <cuda_runtime.h>
#include <cstdint>

#define NROWS 16384
#define CDIM  64
#define KDIM  16
#define DDIM  512
#define MDIM  512
#define NNODES 15

// scratch: per-row codes (4-bit, stored as u8)
__device__ uint8_t g_codes[NROWS * CDIM];

// ---------------------------------------------------------------------------
// Encode: per (row n, subspace c) compute the 4 projected dims, 15 tanh node
// activations, 16 leaf path-scores, argmax (first-max tie-break like jnp).
// ---------------------------------------------------------------------------
__global__ void __launch_bounds__(256) encode_kernel(
    const float* __restrict__ I,
    const float* __restrict__ A,   // (C, 8, 4)
    const float* __restrict__ T,   // (C*15)
    uint8_t* __restrict__ codes)
{
    __shared__ float sA[CDIM * 8 * 4];   // 8 KB
    __shared__ float sT[CDIM * NNODES];  // 3.75 KB

    int tid = threadIdx.x;
    for (int i = tid; i < CDIM * 32; i += 256) sA[i] = A[i];
    for (int i = tid; i < CDIM * NNODES; i += 256) sT[i] = T[i];
    __syncthreads();

    int c = tid & 63;
    int n = blockIdx.x * 4 + (tid >> 6);

    const float4* Ip = (const float4*)(I + (size_t)n * DDIM + c * 8);
    float4 v0 = Ip[0];
    float4 v1 = Ip[1];

    const float* a = sA + c * 32;  // A[c][s][d], d fastest
    float x[4];
#pragma unroll
    for (int d = 0; d < 4; d++) {
        x[d] = v0.x * a[0 * 4 + d] + v0.y * a[1 * 4 + d] +
               v0.z * a[2 * 4 + d] + v0.w * a[3 * 4 + d] +
               v1.x * a[4 * 4 + d] + v1.y * a[5 * 4 + d] +
               v1.z * a[6 * 4 + d] + v1.w * a[7 * 4 + d];
    }

    const int lvl[NNODES] = {0,1,1,2,2,2,2,3,3,3,3,3,3,3,3};
    const float* Tc = sT + c * NNODES;
    float t[NNODES];
#pragma unroll
    for (int i = 0; i < NNODES; i++) t[i] = tanhf(x[lvl[i]] - Tc[i]);

    float best = -3.0e38f;
    int bestk = 0;
#pragma unroll
    for (int k = 0; k < KDIM; k++) {
        float s = 0.0f;
        int node = 0;
#pragma unroll
        for (int l = 0; l < 4; l++) {
            int bit = (k >> (3 - l)) & 1;
            s += bit ? t[node] : -t[node];
            node = 2 * node + 1 + bit;
        }
        if (s > best) { best = s; bestk = k; }  // strict > == first-max tie-break
    }
    codes[(size_t)n * CDIM + c] = (uint8_t)bestk;
}

// ---------------------------------------------------------------------------
// Decode: out[n,m] = sum_c L[m][c][code[n][c]].
// Block = 256 threads = 32 rows (lane-fast) x 8 m-columns. Lane-fast-in-n
// mapping keeps each warp's 32 gathers inside ONE 64B L row (<=2 sectors).
// Codes cached in smem with stride-17 u32 layout (conflict-free).
// Output transposed through smem so stores are 32B-contiguous in m.
// ---------------------------------------------------------------------------
__global__ void __launch_bounds__(256) decode_kernel(
    const uint8_t* __restrict__ codes,
    const float*   __restrict__ L,      // (M, C, K)
    float*         __restrict__ out)    // (N, M)
{
    __shared__ uint32_t scodes[32][17];
    __shared__ float    sout[256];

    int tid   = threadIdx.x;
    int nbase = blockIdx.x * 32;
    int mbase = blockIdx.y * 8;

    // load codes for 32 rows: 2048B = 512 u32, 2 per thread
    {
        int r = tid >> 3;       // 0..31
        int w = tid & 7;        // 0..7
        const uint32_t* src = (const uint32_t*)(codes + (size_t)(nbase + r) * CDIM);
        scodes[r][w]     = src[w];
        scodes[r][w + 8] = src[w + 8];
    }
    __syncthreads();

    int nl = tid & 31;
    int m  = mbase + (tid >> 5);
    const float* Lm = L + (size_t)m * (CDIM * KDIM);

    float acc = 0.0f;
#pragma unroll
    for (int w = 0; w < 16; w++) {
        uint32_t cw = scodes[nl][w];
#pragma unroll
        for (int j = 0; j < 4; j++) {
            int code = (cw >> (8 * j)) & 15;
            acc += __ldg(Lm + (w * 4 + j) * KDIM + code);
        }
    }

    // transpose tile (32n x 8m) so stores are m-contiguous 32B segments
    sout[tid] = acc;
    __syncthreads();
    int on = tid >> 3;   // 0..31
    int om = tid & 7;    // 0..7
    out[(size_t)(nbase + on) * MDIM + mbase + om] = sout[om * 32 + on];
}

extern "C" void kernel_launch(void* const* d_in, const int* in_sizes, int n_in,
                              void* d_out, int out_size)
{
    const float* I = (const float*)d_in[0];
    const float* A = (const float*)d_in[1];
    const float* T = (const float*)d_in[2];
    const float* L = (const float*)d_in[3];
    // d_in[4]=S, d_in[5]=B: structure hardcoded
    float* out = (float*)d_out;

    uint8_t* codes;
    cudaGetSymbolAddress((void**)&codes, g_codes);

    encode_kernel<<<NROWS / 4, 256>>>(I, A, T, codes);

    dim3 grid(NROWS / 32, MDIM / 8);
    decode_kernel<<<grid, 256>>>(codes, L, out);
}

// round 5
// speedup vs baseline: 1.4209x; 1.4209x over previous
#include <cuda_runtime.h>
#include <cstdint>

#define NROWS 16384
#define CDIM  64
#define KDIM  16
#define DDIM  512
#define MDIM  512
#define NNODES 15

// ---------------------------------------------------------------------------
// scratch
// ---------------------------------------------------------------------------
__device__ uint8_t g_codes[NROWS * CDIM];     // 1 MB
__device__ float   g_Lt[CDIM * KDIM * MDIM];  // 2 MB  [c][k][m] (m contiguous)

// ---------------------------------------------------------------------------
// Encode: per (n, c) project 8->4, 15 tanh nodes, 16 leaf scores, argmax.
// Fast tanh.approx + precise-tanhf fallback when top-2 gap < 0.04
// (approx abs err ~1e-3, sum of 4 -> score err < 8e-3; 5x margin).
// ---------------------------------------------------------------------------
__device__ __forceinline__ float ftanh(float x) {
    float y;
    asm("tanh.approx.f32 %0, %1;" : "=f"(y) : "f"(x));
    return y;
}

__global__ void __launch_bounds__(256) encode_kernel(
    const float* __restrict__ I, const float* __restrict__ A,
    const float* __restrict__ T, uint8_t* __restrict__ codes)
{
    __shared__ float sA[CDIM * 32];
    __shared__ float sT[CDIM * NNODES];
    int tid = threadIdx.x;
    for (int i = tid; i < CDIM * 32; i += 256) sA[i] = A[i];
    for (int i = tid; i < CDIM * NNODES; i += 256) sT[i] = T[i];
    __syncthreads();

    int c = tid & 63;
    int n = blockIdx.x * 4 + (tid >> 6);

    const float4* Ip = (const float4*)(I + (size_t)n * DDIM + c * 8);
    float4 v0 = Ip[0], v1 = Ip[1];
    const float* a = sA + c * 32;   // A[c][s][d], d fastest
    float x[4];
#pragma unroll
    for (int d = 0; d < 4; d++)
        x[d] = v0.x * a[d] + v0.y * a[4 + d] + v0.z * a[8 + d] + v0.w * a[12 + d] +
               v1.x * a[16 + d] + v1.y * a[20 + d] + v1.z * a[24 + d] + v1.w * a[28 + d];

    const int lvl[NNODES] = {0,1,1,2,2,2,2,3,3,3,3,3,3,3,3};
    const float* Tc = sT + c * NNODES;

    float h[NNODES], t[NNODES];
#pragma unroll
    for (int i = 0; i < NNODES; i++) { h[i] = x[lvl[i]] - Tc[i]; t[i] = ftanh(h[i]); }

    float best = -3.0e38f, second = -3.0e38f;
    int bestk = 0;
#pragma unroll
    for (int k = 0; k < KDIM; k++) {
        float s = 0.0f; int node = 0;
#pragma unroll
        for (int l = 0; l < 4; l++) {
            int bit = (k >> (3 - l)) & 1;
            s += bit ? t[node] : -t[node];
            node = 2 * node + 1 + bit;
        }
        if (s > best) { second = best; best = s; bestk = k; }
        else if (s > second) { second = s; }
    }
    if (best - second < 0.04f) {   // near-tie: exact tanh, jnp first-max tie-break
#pragma unroll
        for (int i = 0; i < NNODES; i++) t[i] = tanhf(h[i]);
        best = -3.0e38f; bestk = 0;
#pragma unroll
        for (int k = 0; k < KDIM; k++) {
            float s = 0.0f; int node = 0;
#pragma unroll
            for (int l = 0; l < 4; l++) {
                int bit = (k >> (3 - l)) & 1;
                s += bit ? t[node] : -t[node];
                node = 2 * node + 1 + bit;
            }
            if (s > best) { best = s; bestk = k; }
        }
    }
    codes[(size_t)n * CDIM + c] = (uint8_t)bestk;
}

// ---------------------------------------------------------------------------
// L ([m][ck], ck = c*16+k) -> Lt ([ck][m])
// ---------------------------------------------------------------------------
__global__ void __launch_bounds__(256) transpose_kernel(
    const float* __restrict__ L, float* __restrict__ Lt)
{
    int i = blockIdx.x * 256 + threadIdx.x;   // 0 .. 524287
    int ck = i >> 9, m = i & 511;
    Lt[i] = L[(size_t)m * 1024 + ck];
}

// ---------------------------------------------------------------------------
// Decode: out[n][m] = sum_c Lt[c][code(n,c)][m].
// One warp per row n. Codes are warp-uniform (shfl-broadcast), so all loads
// are dense, coalesced LDG.128 over the contiguous 512-float LUT rows.
// ---------------------------------------------------------------------------
__global__ void __launch_bounds__(256) decode_fb_kernel(
    const uint8_t* __restrict__ codes,
    const float* __restrict__ Lt,
    float* __restrict__ out)
{
    int warp = (blockIdx.x * 256 + threadIdx.x) >> 5;   // == n
    int lane = threadIdx.x & 31;
    int n = warp;

    const uint32_t* cwp = (const uint32_t*)(codes + (size_t)n * CDIM);
    uint32_t cw = (lane < 16) ? cwp[lane] : 0;

    float4 acc0 = {0,0,0,0}, acc1 = {0,0,0,0}, acc2 = {0,0,0,0}, acc3 = {0,0,0,0};
#pragma unroll
    for (int w = 0; w < 16; w++) {
        uint32_t word = __shfl_sync(0xffffffffu, cw, w);
#pragma unroll
        for (int b = 0; b < 4; b++) {
            int c = w * 4 + b;
            int code = (word >> (8 * b)) & 15;
            const float4* p = (const float4*)(Lt + ((size_t)(c * 16 + code) << 9)) + lane;
            float4 v0 = p[0], v1 = p[32], v2 = p[64], v3 = p[96];
            acc0.x += v0.x; acc0.y += v0.y; acc0.z += v0.z; acc0.w += v0.w;
            acc1.x += v1.x; acc1.y += v1.y; acc1.z += v1.z; acc1.w += v1.w;
            acc2.x += v2.x; acc2.y += v2.y; acc2.z += v2.z; acc2.w += v2.w;
            acc3.x += v3.x; acc3.y += v3.y; acc3.z += v3.z; acc3.w += v3.w;
        }
    }
    float4* op = (float4*)(out + (size_t)n * MDIM) + lane;
    op[0] = acc0; op[32] = acc1; op[64] = acc2; op[96] = acc3;
}

// ---------------------------------------------------------------------------
extern "C" void kernel_launch(void* const* d_in, const int* in_sizes, int n_in,
                              void* d_out, int out_size)
{
    const float* I = (const float*)d_in[0];
    const float* A = (const float*)d_in[1];
    const float* T = (const float*)d_in[2];
    const float* L = (const float*)d_in[3];
    float* out = (float*)d_out;

    uint8_t* codes;
    float* Lt;
    cudaGetSymbolAddress((void**)&codes, g_codes);
    cudaGetSymbolAddress((void**)&Lt, g_Lt);

    encode_kernel<<<NROWS / 4, 256>>>(I, A, T, codes);
    transpose_kernel<<<CDIM * KDIM * MDIM / 256, 256>>>(L, Lt);
    decode_fb_kernel<<<NROWS * 32 / 256, 256>>>(codes, Lt, out);
}

// round 6
// speedup vs baseline: 1.5378x; 1.0823x over previous
#include <cuda_runtime.h>
#include <cstdint>

#define NROWS 16384
#define CDIM  64
#define KDIM  16
#define DDIM  512
#define MDIM  512
#define NNODES 15

// ---------------------------------------------------------------------------
// scratch
// ---------------------------------------------------------------------------
__device__ uint8_t g_codes[NROWS * CDIM];     // 1 MB
__device__ float   g_Lt[CDIM * KDIM * MDIM];  // 2 MB  [c][k][m] (m contiguous)

// ---------------------------------------------------------------------------
// Encode: per (n, c) project 8->4, 15 tanh nodes, 16 leaf scores, argmax.
// Fast tanh.approx + precise-tanhf fallback when top-2 gap < 0.04.
// smem staged c-FASTEST so lanes (distinct c) hit distinct banks.
// ---------------------------------------------------------------------------
__device__ __forceinline__ float ftanh(float x) {
    float y;
    asm("tanh.approx.f32 %0, %1;" : "=f"(y) : "f"(x));
    return y;
}

__global__ void __launch_bounds__(512) encode_kernel(
    const float* __restrict__ I, const float* __restrict__ A,
    const float* __restrict__ T, uint8_t* __restrict__ codes)
{
    // sA[idx][c]: idx = s*4+d (0..31), c fastest (64) -> conflict-free lane reads
    __shared__ float sA[32 * CDIM];
    __shared__ float sT[NNODES * CDIM];
    int tid = threadIdx.x;
    for (int i = tid; i < CDIM * 32; i += 512) {
        int c = i >> 5, idx = i & 31;            // source A[c][idx]
        sA[idx * CDIM + c] = A[i];
    }
    for (int i = tid; i < CDIM * NNODES; i += 512) {
        int c = i / NNODES, node = i - c * NNODES;   // source T[c*15+node]
        sT[node * CDIM + c] = T[i];
    }
    __syncthreads();

    int c = tid & 63;
    int n = blockIdx.x * 8 + (tid >> 6);

    const float4* Ip = (const float4*)(I + (size_t)n * DDIM + c * 8);
    float4 v0 = Ip[0], v1 = Ip[1];

    float x[4];
#pragma unroll
    for (int d = 0; d < 4; d++)
        x[d] = v0.x * sA[(0 * 4 + d) * CDIM + c] + v0.y * sA[(1 * 4 + d) * CDIM + c] +
               v0.z * sA[(2 * 4 + d) * CDIM + c] + v0.w * sA[(3 * 4 + d) * CDIM + c] +
               v1.x * sA[(4 * 4 + d) * CDIM + c] + v1.y * sA[(5 * 4 + d) * CDIM + c] +
               v1.z * sA[(6 * 4 + d) * CDIM + c] + v1.w * sA[(7 * 4 + d) * CDIM + c];

    const int lvl[NNODES] = {0,1,1,2,2,2,2,3,3,3,3,3,3,3,3};

    float h[NNODES], t[NNODES];
#pragma unroll
    for (int i = 0; i < NNODES; i++) {
        h[i] = x[lvl[i]] - sT[i * CDIM + c];
        t[i] = ftanh(h[i]);
    }

    float best = -3.0e38f, second = -3.0e38f;
    int bestk = 0;
#pragma unroll
    for (int k = 0; k < KDIM; k++) {
        float s = 0.0f; int node = 0;
#pragma unroll
        for (int l = 0; l < 4; l++) {
            int bit = (k >> (3 - l)) & 1;
            s += bit ? t[node] : -t[node];
            node = 2 * node + 1 + bit;
        }
        if (s > best) { second = best; best = s; bestk = k; }
        else if (s > second) { second = s; }
    }
    if (best - second < 0.04f) {   // near-tie: exact tanh, jnp first-max tie-break
#pragma unroll
        for (int i = 0; i < NNODES; i++) t[i] = tanhf(h[i]);
        best = -3.0e38f; bestk = 0;
#pragma unroll
        for (int k = 0; k < KDIM; k++) {
            float s = 0.0f; int node = 0;
#pragma unroll
            for (int l = 0; l < 4; l++) {
                int bit = (k >> (3 - l)) & 1;
                s += bit ? t[node] : -t[node];
                node = 2 * node + 1 + bit;
            }
            if (s > best) { best = s; bestk = k; }
        }
    }
    codes[(size_t)n * CDIM + c] = (uint8_t)bestk;
}

// ---------------------------------------------------------------------------
// L ([m][ck], ck = c*16+k) -> Lt ([ck][m])
// ---------------------------------------------------------------------------
__global__ void __launch_bounds__(256) transpose_kernel(
    const float* __restrict__ L, float* __restrict__ Lt)
{
    int i = blockIdx.x * 256 + threadIdx.x;   // 0 .. 524287
    int ck = i >> 9, m = i & 511;
    Lt[i] = L[(size_t)m * 1024 + ck];
}

// ---------------------------------------------------------------------------
// Decode: out[n][m] = sum_c Lt[c][code(n,c)][m].
// One warp per row n. Codes are warp-uniform (shfl-broadcast) -> dense,
// coalesced LDG.128 over contiguous 512-float LUT rows.
// ---------------------------------------------------------------------------
__global__ void __launch_bounds__(256) decode_fb_kernel(
    const uint8_t* __restrict__ codes,
    const float* __restrict__ Lt,
    float* __restrict__ out)
{
    int warp = (blockIdx.x * 256 + threadIdx.x) >> 5;   // == n
    int lane = threadIdx.x & 31;
    int n = warp;

    const uint32_t* cwp = (const uint32_t*)(codes + (size_t)n * CDIM);
    uint32_t cw = (lane < 16) ? cwp[lane] : 0;

    float4 acc0 = {0,0,0,0}, acc1 = {0,0,0,0}, acc2 = {0,0,0,0}, acc3 = {0,0,0,0};
#pragma unroll
    for (int w = 0; w < 16; w++) {
        uint32_t word = __shfl_sync(0xffffffffu, cw, w);
#pragma unroll
        for (int b = 0; b < 4; b++) {
            int c = w * 4 + b;
            int code = (word >> (8 * b)) & 15;
            const float4* p = (const float4*)(Lt + ((size_t)(c * 16 + code) << 9)) + lane;
            float4 v0 = p[0], v1 = p[32], v2 = p[64], v3 = p[96];
            acc0.x += v0.x; acc0.y += v0.y; acc0.z += v0.z; acc0.w += v0.w;
            acc1.x += v1.x; acc1.y += v1.y; acc1.z += v1.z; acc1.w += v1.w;
            acc2.x += v2.x; acc2.y += v2.y; acc2.z += v2.z; acc2.w += v2.w;
            acc3.x += v3.x; acc3.y += v3.y; acc3.z += v3.z; acc3.w += v3.w;
        }
    }
    float4* op = (float4*)(out + (size_t)n * MDIM) + lane;
    op[0] = acc0; op[32] = acc1; op[64] = acc2; op[96] = acc3;
}

// ---------------------------------------------------------------------------
extern "C" void kernel_launch(void* const* d_in, const int* in_sizes, int n_in,
                              void* d_out, int out_size)
{
    const float* I = (const float*)d_in[0];
    const float* A = (const float*)d_in[1];
    const float* T = (const float*)d_in[2];
    const float* L = (const float*)d_in[3];
    float* out = (float*)d_out;

    uint8_t* codes;
    float* Lt;
    cudaGetSymbolAddress((void**)&codes, g_codes);
    cudaGetSymbolAddress((void**)&Lt, g_Lt);

    encode_kernel<<<NROWS / 8, 512>>>(I, A, T, codes);
    transpose_kernel<<<CDIM * KDIM * MDIM / 256, 256>>>(L, Lt);
    decode_fb_kernel<<<NROWS * 32 / 256, 256>>>(codes, Lt, out);
}

// round 13
// speedup vs baseline: 1.9324x; 1.2566x over previous
#include <cuda_runtime.h>
#include <cuda_fp16.h>
#include <cstdint>

#define NROWS 16384
#define CDIM  64
#define KDIM  16
#define DDIM  512
#define MDIM  512
#define NNODES 15

// ---------------------------------------------------------------------------
// scratch
// ---------------------------------------------------------------------------
__device__ uint8_t g_codes[NROWS * CDIM];        // 1 MB
__device__ __half  g_Lh[CDIM * KDIM * MDIM];     // 1 MB  [c][k][m] fp16, m contiguous

// ---------------------------------------------------------------------------
// fast precise-enough tanh: 1 - 2/(1+exp2(2|x|*log2e)), sign restored.
// ex2.approx rel err 2^-22, rcp.approx 2^-23  ->  abs err < ~5e-7.
// ---------------------------------------------------------------------------
__device__ __forceinline__ float tanh_fast(float x) {
    float ax = fabsf(x);
    float e;
    asm("ex2.approx.f32 %0, %1;" : "=f"(e) : "f"(ax * 2.8853900817779268f));
    float r;
    asm("rcp.approx.f32 %0, %1;" : "=f"(r) : "f"(1.0f + e));
    float t = fmaf(-2.0f, r, 1.0f);
    return copysignf(t, x);
}

// ---------------------------------------------------------------------------
// Encode v3: one thread = one subspace c, 8 rows. A,T register-resident
// (no smem). Partial-sum tree (30 adds) for the 16 leaf scores.
// Near-tie fallback (gap < 1e-5) to precise tanhf — probability ~1e-5.
// ---------------------------------------------------------------------------
__global__ void __launch_bounds__(256) encode_kernel(
    const float* __restrict__ I, const float* __restrict__ A,
    const float* __restrict__ T, uint8_t* __restrict__ codes)
{
    const int c = threadIdx.x & 63;
    const int q = threadIdx.x >> 6;          // 0..3 row streams
    const int n0 = blockIdx.x * 32 + q * 8;

    // A[c][s][d]: 32 consecutive floats
    float a[32];
    const float4* Ap = (const float4*)(A + c * 32);
#pragma unroll
    for (int i = 0; i < 8; i++) {
        float4 v = Ap[i];
        a[i * 4 + 0] = v.x; a[i * 4 + 1] = v.y; a[i * 4 + 2] = v.z; a[i * 4 + 3] = v.w;
    }
    float tt[NNODES];
#pragma unroll
    for (int i = 0; i < NNODES; i++) tt[i] = T[c * NNODES + i];

    const int lvl[NNODES] = {0,1,1,2,2,2,2,3,3,3,3,3,3,3,3};

#pragma unroll 1
    for (int r = 0; r < 8; r++) {
        const int n = n0 + r;
        const float4* Ip = (const float4*)(I + (size_t)n * DDIM + c * 8);
        float4 v0 = Ip[0], v1 = Ip[1];

        float x[4];
#pragma unroll
        for (int d = 0; d < 4; d++)
            x[d] = v0.x * a[d]      + v0.y * a[4 + d]  + v0.z * a[8 + d]  + v0.w * a[12 + d] +
                   v1.x * a[16 + d] + v1.y * a[20 + d] + v1.z * a[24 + d] + v1.w * a[28 + d];

        float h[NNODES], t[NNODES];
#pragma unroll
        for (int i = 0; i < NNODES; i++) {
            h[i] = x[lvl[i]] - tt[i];
            t[i] = tanh_fast(h[i]);
        }

        // partial-sum tree: p1(2) -> p2(4) -> p3(8) -> scores(16)
        float p2[4], p3[8], s[16];
        p2[0] = -t[0] - t[1];  p2[1] = -t[0] + t[1];
        p2[2] =  t[0] - t[2];  p2[3] =  t[0] + t[2];
#pragma unroll
        for (int j = 0; j < 4; j++) {
            p3[2 * j]     = p2[j] - t[3 + j];
            p3[2 * j + 1] = p2[j] + t[3 + j];
        }
#pragma unroll
        for (int j = 0; j < 8; j++) {
            s[2 * j]     = p3[j] - t[7 + j];
            s[2 * j + 1] = p3[j] + t[7 + j];
        }

        float best = -3.0e38f, second = -3.0e38f;
        int bestk = 0;
#pragma unroll
        for (int k = 0; k < KDIM; k++) {
            if (s[k] > best) { second = best; best = s[k]; bestk = k; }
            else if (s[k] > second) second = s[k];
        }

        if (best - second < 1e-5f) {   // ~never: exact tanh, jnp first-max order
#pragma unroll
            for (int i = 0; i < NNODES; i++) t[i] = tanhf(h[i]);
            p2[0] = -t[0] - t[1];  p2[1] = -t[0] + t[1];
            p2[2] =  t[0] - t[2];  p2[3] =  t[0] + t[2];
#pragma unroll
            for (int j = 0; j < 4; j++) {
                p3[2 * j]     = p2[j] - t[3 + j];
                p3[2 * j + 1] = p2[j] + t[3 + j];
            }
#pragma unroll
            for (int j = 0; j < 8; j++) {
                s[2 * j]     = p3[j] - t[7 + j];
                s[2 * j + 1] = p3[j] + t[7 + j];
            }
            best = -3.0e38f; bestk = 0;
#pragma unroll
            for (int k = 0; k < KDIM; k++)
                if (s[k] > best) { best = s[k]; bestk = k; }
        }
        codes[(size_t)n * CDIM + c] = (uint8_t)bestk;
    }
}

// ---------------------------------------------------------------------------
// L ([m][ck] f32) -> Lh ([ck][m] fp16). Reads coalesced; 1 MB result.
// ---------------------------------------------------------------------------
__global__ void __launch_bounds__(256) convert_kernel(
    const float* __restrict__ L, __half* __restrict__ Lh)
{
    int i = blockIdx.x * 256 + threadIdx.x;   // 0 .. 524287
    int m = i >> 10, ck = i & 1023;
    Lh[(size_t)ck * MDIM + m] = __float2half(L[i]);
}

// ---------------------------------------------------------------------------
// Decode: out[n][m] = sum_c Lh[c][code(n,c)][m], fp32 accumulation.
// One warp per n; codes warp-uniform -> dense LDG.64 over 1KB fp16 rows.
// Per lane: acc m = 4*lane + 128*J + {0..3}  ->  4x STG.128.
// ---------------------------------------------------------------------------
__global__ void __launch_bounds__(256) decode_kernel(
    const uint8_t* __restrict__ codes,
    const __half* __restrict__ Lh,
    float* __restrict__ out)
{
    const int warp = (blockIdx.x * 256 + threadIdx.x) >> 5;   // == n
    const int lane = threadIdx.x & 31;
    const int n = warp;

    const uint32_t* cwp = (const uint32_t*)(codes + (size_t)n * CDIM);
    uint32_t cw = (lane < 16) ? cwp[lane] : 0;

    float4 acc[4];
#pragma unroll
    for (int J = 0; J < 4; J++) acc[J] = make_float4(0.f, 0.f, 0.f, 0.f);

#pragma unroll
    for (int w = 0; w < 16; w++) {
        uint32_t word = __shfl_sync(0xffffffffu, cw, w);
#pragma unroll
        for (int b = 0; b < 4; b++) {
            int c = w * 4 + b;
            int code = (word >> (8 * b)) & 15;
            const uint2* row = (const uint2*)(Lh + ((size_t)(c * 16 + code) << 9));
#pragma unroll
            for (int J = 0; J < 4; J++) {
                uint2 v = row[lane + 32 * J];
                __half2 h0 = *(__half2*)&v.x;
                __half2 h1 = *(__half2*)&v.y;
                float2 f0 = __half22float2(h0);
                float2 f1 = __half22float2(h1);
                acc[J].x += f0.x; acc[J].y += f0.y;
                acc[J].z += f1.x; acc[J].w += f1.y;
            }
        }
    }

    float4* op = (float4*)(out + (size_t)n * MDIM);
#pragma unroll
    for (int J = 0; J < 4; J++) op[lane + 32 * J] = acc[J];
}

// ---------------------------------------------------------------------------
extern "C" void kernel_launch(void* const* d_in, const int* in_sizes, int n_in,
                              void* d_out, int out_size)
{
    const float* I = (const float*)d_in[0];
    const float* A = (const float*)d_in[1];
    const float* T = (const float*)d_in[2];
    const float* L = (const float*)d_in[3];
    float* out = (float*)d_out;

    uint8_t* codes;
    __half* Lh;
    cudaGetSymbolAddress((void**)&codes, g_codes);
    cudaGetSymbolAddress((void**)&Lh, g_Lh);

    encode_kernel<<<NROWS / 32, 256>>>(I, A, T, codes);
    convert_kernel<<<MDIM * 1024 / 256, 256>>>(L, Lh);
    decode_kernel<<<NROWS * 32 / 256, 256>>>(codes, Lh, out);
}

// round 14
// speedup vs baseline: 2.1860x; 1.1312x over previous
#include <cuda_runtime.h>
#include <cuda_fp16.h>
#include <cstdint>

#define NROWS 16384
#define CDIM  64
#define KDIM  16
#define DDIM  512
#define MDIM  512
#define NNODES 15

// ---------------------------------------------------------------------------
// scratch
// ---------------------------------------------------------------------------
__device__ uint8_t g_codes[NROWS * CDIM];        // 1 MB
__device__ __half  g_Lh[CDIM * KDIM * MDIM];     // 1 MB  [c][k][m] fp16, m contiguous

// ---------------------------------------------------------------------------
// tanh ladder: approx (1 MUFU) -> ex2+rcp (2 MUFU, err ~5e-7) -> tanhf
// ---------------------------------------------------------------------------
__device__ __forceinline__ float tanh_approx(float x) {
    float y;
    asm("tanh.approx.f32 %0, %1;" : "=f"(y) : "f"(x));
    return y;
}
__device__ __forceinline__ float tanh_fast(float x) {
    float ax = fabsf(x);
    float e;
    asm("ex2.approx.f32 %0, %1;" : "=f"(e) : "f"(ax * 2.8853900817779268f));
    float r;
    asm("rcp.approx.f32 %0, %1;" : "=f"(r) : "f"(1.0f + e));
    float t = fmaf(-2.0f, r, 1.0f);
    return copysignf(t, x);
}

// leaf scores via partial-sum tree (30 adds), argmax with runner-up
__device__ __forceinline__ void leaf_argmax(const float* t, float& best,
                                            float& second, int& bestk) {
    float p2[4], p3[8], s[16];
    p2[0] = -t[0] - t[1];  p2[1] = -t[0] + t[1];
    p2[2] =  t[0] - t[2];  p2[3] =  t[0] + t[2];
#pragma unroll
    for (int j = 0; j < 4; j++) {
        p3[2 * j]     = p2[j] - t[3 + j];
        p3[2 * j + 1] = p2[j] + t[3 + j];
    }
#pragma unroll
    for (int j = 0; j < 8; j++) {
        s[2 * j]     = p3[j] - t[7 + j];
        s[2 * j + 1] = p3[j] + t[7 + j];
    }
    best = -3.0e38f; second = -3.0e38f; bestk = 0;
#pragma unroll
    for (int k = 0; k < KDIM; k++) {
        if (s[k] > best) { second = best; best = s[k]; bestk = k; }
        else if (s[k] > second) second = s[k];
    }
}

// ---------------------------------------------------------------------------
// Encode: R6 structure (smem A/T, c-fastest = conflict-free, low regs, high
// occ) + tanh.approx primary + per-thread two-stage refine.
// ---------------------------------------------------------------------------
__global__ void __launch_bounds__(512) encode_kernel(
    const float* __restrict__ I, const float* __restrict__ A,
    const float* __restrict__ T, uint8_t* __restrict__ codes)
{
    __shared__ float sA[32 * CDIM];
    __shared__ float sT[NNODES * CDIM];
    int tid = threadIdx.x;
    for (int i = tid; i < CDIM * 32; i += 512) {
        int c = i >> 5, idx = i & 31;
        sA[idx * CDIM + c] = A[i];
    }
    for (int i = tid; i < CDIM * NNODES; i += 512) {
        int c = i / NNODES, node = i - c * NNODES;
        sT[node * CDIM + c] = T[i];
    }
    __syncthreads();

    const int c = tid & 63;
    const int n = blockIdx.x * 8 + (tid >> 6);

    const float4* Ip = (const float4*)(I + (size_t)n * DDIM + c * 8);
    float4 v0 = Ip[0], v1 = Ip[1];

    float x[4];
#pragma unroll
    for (int d = 0; d < 4; d++)
        x[d] = v0.x * sA[(0 * 4 + d) * CDIM + c] + v0.y * sA[(1 * 4 + d) * CDIM + c] +
               v0.z * sA[(2 * 4 + d) * CDIM + c] + v0.w * sA[(3 * 4 + d) * CDIM + c] +
               v1.x * sA[(4 * 4 + d) * CDIM + c] + v1.y * sA[(5 * 4 + d) * CDIM + c] +
               v1.z * sA[(6 * 4 + d) * CDIM + c] + v1.w * sA[(7 * 4 + d) * CDIM + c];

    const int lvl[NNODES] = {0,1,1,2,2,2,2,3,3,3,3,3,3,3,3};
    float h[NNODES], t[NNODES];
#pragma unroll
    for (int i = 0; i < NNODES; i++) {
        h[i] = x[lvl[i]] - sT[i * CDIM + c];
        t[i] = tanh_approx(h[i]);
    }

    float best, second;
    int bestk;
    leaf_argmax(t, best, second, bestk);

    if (best - second < 0.02f) {          // refine: ex2+rcp, err ~5e-7
#pragma unroll
        for (int i = 0; i < NNODES; i++) t[i] = tanh_fast(h[i]);
        leaf_argmax(t, best, second, bestk);
        if (best - second < 1e-4f) {      // ~never: exact tanhf
#pragma unroll
            for (int i = 0; i < NNODES; i++) t[i] = tanhf(h[i]);
            leaf_argmax(t, best, second, bestk);
        }
    }
    codes[(size_t)n * CDIM + c] = (uint8_t)bestk;
}

// ---------------------------------------------------------------------------
// Transpose+convert: L [m][ck] f32 -> Lh [ck][m] fp16, smem-tiled 32x32
// so both global sides are coalesced.
// ---------------------------------------------------------------------------
__global__ void __launch_bounds__(256) convert_kernel(
    const float* __restrict__ L, __half* __restrict__ Lh)
{
    __shared__ __half st[32][33];
    const int m0  = blockIdx.x * 32;      // 16 blocks in m
    const int ck0 = blockIdx.y * 32;      // 32 blocks in ck
    const int tx = threadIdx.x & 31, ty8 = threadIdx.x >> 5;   // 32 x 8
#pragma unroll
    for (int r = 0; r < 4; r++) {
        int m = m0 + ty8 + r * 8;
        st[tx][ty8 + r * 8] = __float2half(L[(size_t)m * 1024 + ck0 + tx]);
    }
    __syncthreads();
#pragma unroll
    for (int r = 0; r < 4; r++) {
        int ck = ck0 + ty8 + r * 8;
        Lh[(size_t)ck * MDIM + m0 + tx] = st[ty8 + r * 8][tx];
    }
}

// ---------------------------------------------------------------------------
// Decode: out[n][m] = sum_c Lh[c][code(n,c)][m].
// One warp per n; codes warp-uniform. LDG.128 dense rows; HADD2 group
// accumulation over 4 consecutive c (one code word), flushed to fp32.
// ---------------------------------------------------------------------------
__global__ void __launch_bounds__(256) decode_kernel(
    const uint8_t* __restrict__ codes,
    const __half* __restrict__ Lh,
    float* __restrict__ out)
{
    const int n    = (blockIdx.x * 256 + threadIdx.x) >> 5;
    const int lane = threadIdx.x & 31;

    const uint32_t* cwp = (const uint32_t*)(codes + (size_t)n * CDIM);
    uint32_t cw = (lane < 16) ? cwp[lane] : 0;

    float acc[16];
#pragma unroll
    for (int i = 0; i < 16; i++) acc[i] = 0.0f;

#pragma unroll 4
    for (int w = 0; w < 16; w++) {
        uint32_t word = __shfl_sync(0xffffffffu, cw, w);

        __half2 hacc[8];
#pragma unroll
        for (int i = 0; i < 8; i++) hacc[i] = __half2half2(__ushort_as_half(0));

#pragma unroll
        for (int b = 0; b < 4; b++) {
            int c = w * 4 + b;
            int code = (word >> (8 * b)) & 15;
            const uint4* row = (const uint4*)(Lh + ((size_t)(c * 16 + code) << 9));
#pragma unroll
            for (int J = 0; J < 2; J++) {
                uint4 v = row[lane + 32 * J];
                hacc[J * 4 + 0] = __hadd2(hacc[J * 4 + 0], *(__half2*)&v.x);
                hacc[J * 4 + 1] = __hadd2(hacc[J * 4 + 1], *(__half2*)&v.y);
                hacc[J * 4 + 2] = __hadd2(hacc[J * 4 + 2], *(__half2*)&v.z);
                hacc[J * 4 + 3] = __hadd2(hacc[J * 4 + 3], *(__half2*)&v.w);
            }
        }
        // flush group of 4 c's to fp32
#pragma unroll
        for (int J = 0; J < 2; J++)
#pragma unroll
            for (int p = 0; p < 4; p++) {
                float2 f = __half22float2(hacc[J * 4 + p]);
                acc[J * 8 + p * 2]     += f.x;
                acc[J * 8 + p * 2 + 1] += f.y;
            }
    }

    // thread covers m = lane*8..+8 (J=0) and 256+lane*8..+8 (J=1)
    float4* op0 = (float4*)(out + (size_t)n * MDIM + lane * 8);
    op0[0] = make_float4(acc[0], acc[1], acc[2], acc[3]);
    op0[1] = make_float4(acc[4], acc[5], acc[6], acc[7]);
    float4* op1 = (float4*)(out + (size_t)n * MDIM + 256 + lane * 8);
    op1[0] = make_float4(acc[8], acc[9], acc[10], acc[11]);
    op1[1] = make_float4(acc[12], acc[13], acc[14], acc[15]);
}

// ---------------------------------------------------------------------------
extern "C" void kernel_launch(void* const* d_in, const int* in_sizes, int n_in,
                              void* d_out, int out_size)
{
    const float* I = (const float*)d_in[0];
    const float* A = (const float*)d_in[1];
    const float* T = (const float*)d_in[2];
    const float* L = (const float*)d_in[3];
    float* out = (float*)d_out;

    uint8_t* codes;
    __half* Lh;
    cudaGetSymbolAddress((void**)&codes, g_codes);
    cudaGetSymbolAddress((void**)&Lh, g_Lh);

    encode_kernel<<<NROWS / 8, 512>>>(I, A, T, codes);
    dim3 tgrid(MDIM / 32, 1024 / 32);
    convert_kernel<<<tgrid, 256>>>(L, Lh);
    decode_kernel<<<NROWS * 32 / 256, 256>>>(codes, Lh, out);
}

// round 15
// speedup vs baseline: 2.2476x; 1.0282x over previous
#include <cuda_runtime.h>
#include <cuda_fp16.h>
#include <cstdint>

#define NROWS 16384
#define CDIM  64
#define KDIM  16
#define DDIM  512
#define MDIM  512
#define NNODES 15

// ---------------------------------------------------------------------------
// scratch
// ---------------------------------------------------------------------------
__device__ uint8_t g_codes[NROWS * CDIM];        // 1 MB
__device__ __half  g_Lh[CDIM * KDIM * MDIM];     // 1 MB  [c][k][m] fp16, m contiguous

// ---------------------------------------------------------------------------
// tanh via e = exp2(2x*log2e):  t = (e-1)/(e+1).  Sign-free (no abs/copysign),
// 6 instrs, abs err < ~3e-7 (ex2/rcp rel err 2^-22). Overflow only at |x|>44.
// ---------------------------------------------------------------------------
__device__ __forceinline__ float tanh_e(float x) {
    float e;
    asm("ex2.approx.f32 %0, %1;" : "=f"(e) : "f"(x * 2.8853900817779268f));
    float r;
    asm("rcp.approx.f32 %0, %1;" : "=f"(r) : "f"(e + 1.0f));
    return (e - 1.0f) * r;
}

// leaf scores via partial-sum tree (30 adds), argmax with runner-up
__device__ __forceinline__ void leaf_argmax(const float* t, float& best,
                                            float& second, int& bestk) {
    float p2[4], p3[8], s[16];
    p2[0] = -t[0] - t[1];  p2[1] = -t[0] + t[1];
    p2[2] =  t[0] - t[2];  p2[3] =  t[0] + t[2];
#pragma unroll
    for (int j = 0; j < 4; j++) {
        p3[2 * j]     = p2[j] - t[3 + j];
        p3[2 * j + 1] = p2[j] + t[3 + j];
    }
#pragma unroll
    for (int j = 0; j < 8; j++) {
        s[2 * j]     = p3[j] - t[7 + j];
        s[2 * j + 1] = p3[j] + t[7 + j];
    }
    best = -3.0e38f; second = -3.0e38f; bestk = 0;
#pragma unroll
    for (int k = 0; k < KDIM; k++) {
        if (s[k] > best) { second = best; best = s[k]; bestk = k; }
        else if (s[k] > second) second = s[k];
    }
}

// ---------------------------------------------------------------------------
// Encode: smem A/T (c-fastest, conflict-free), tanh_e single accurate pass,
// tanhf safety rung only below gap 1e-4 (~never; no warp-wide refine pass).
// ---------------------------------------------------------------------------
__global__ void __launch_bounds__(512) encode_kernel(
    const float* __restrict__ I, const float* __restrict__ A,
    const float* __restrict__ T, uint8_t* __restrict__ codes)
{
    __shared__ float sA[32 * CDIM];
    __shared__ float sT[NNODES * CDIM];
    int tid = threadIdx.x;
    for (int i = tid; i < CDIM * 32; i += 512) {
        int c = i >> 5, idx = i & 31;
        sA[idx * CDIM + c] = A[i];
    }
    for (int i = tid; i < CDIM * NNODES; i += 512) {
        int c = i / NNODES, node = i - c * NNODES;
        sT[node * CDIM + c] = T[i];
    }
    __syncthreads();

    const int c = tid & 63;
    const int n = blockIdx.x * 8 + (tid >> 6);

    const float4* Ip = (const float4*)(I + (size_t)n * DDIM + c * 8);
    float4 v0 = Ip[0], v1 = Ip[1];

    float x[4];
#pragma unroll
    for (int d = 0; d < 4; d++)
        x[d] = v0.x * sA[(0 * 4 + d) * CDIM + c] + v0.y * sA[(1 * 4 + d) * CDIM + c] +
               v0.z * sA[(2 * 4 + d) * CDIM + c] + v0.w * sA[(3 * 4 + d) * CDIM + c] +
               v1.x * sA[(4 * 4 + d) * CDIM + c] + v1.y * sA[(5 * 4 + d) * CDIM + c] +
               v1.z * sA[(6 * 4 + d) * CDIM + c] + v1.w * sA[(7 * 4 + d) * CDIM + c];

    const int lvl[NNODES] = {0,1,1,2,2,2,2,3,3,3,3,3,3,3,3};
    float h[NNODES], t[NNODES];
#pragma unroll
    for (int i = 0; i < NNODES; i++) {
        h[i] = x[lvl[i]] - sT[i * CDIM + c];
        t[i] = tanh_e(h[i]);
    }

    float best, second;
    int bestk;
    leaf_argmax(t, best, second, bestk);

    if (best - second < 1e-4f) {   // safety rung, ~never taken
#pragma unroll
        for (int i = 0; i < NNODES; i++) t[i] = tanhf(h[i]);
        leaf_argmax(t, best, second, bestk);
    }
    codes[(size_t)n * CDIM + c] = (uint8_t)bestk;
}

// ---------------------------------------------------------------------------
// Transpose+convert: L [m][ck] f32 -> Lh [ck][m] fp16, smem-tiled 32x32
// ---------------------------------------------------------------------------
__global__ void __launch_bounds__(256) convert_kernel(
    const float* __restrict__ L, __half* __restrict__ Lh)
{
    __shared__ __half st[32][33];
    const int m0  = blockIdx.x * 32;
    const int ck0 = blockIdx.y * 32;
    const int tx = threadIdx.x & 31, ty8 = threadIdx.x >> 5;   // 32 x 8
#pragma unroll
    for (int r = 0; r < 4; r++) {
        int m = m0 + ty8 + r * 8;
        st[tx][ty8 + r * 8] = __float2half(L[(size_t)m * 1024 + ck0 + tx]);
    }
    __syncthreads();
#pragma unroll
    for (int r = 0; r < 4; r++) {
        int ck = ck0 + ty8 + r * 8;
        Lh[(size_t)ck * MDIM + m0 + tx] = st[ty8 + r * 8][tx];
    }
}

// ---------------------------------------------------------------------------
// Decode (unchanged from R14): one warp per n; warp-uniform codes; LDG.128
// dense fp16 rows; HADD2 group accumulation (4 c's), fp32 flush.
// ---------------------------------------------------------------------------
__global__ void __launch_bounds__(256) decode_kernel(
    const uint8_t* __restrict__ codes,
    const __half* __restrict__ Lh,
    float* __restrict__ out)
{
    const int n    = (blockIdx.x * 256 + threadIdx.x) >> 5;
    const int lane = threadIdx.x & 31;

    const uint32_t* cwp = (const uint32_t*)(codes + (size_t)n * CDIM);
    uint32_t cw = (lane < 16) ? cwp[lane] : 0;

    float acc[16];
#pragma unroll
    for (int i = 0; i < 16; i++) acc[i] = 0.0f;

#pragma unroll 4
    for (int w = 0; w < 16; w++) {
        uint32_t word = __shfl_sync(0xffffffffu, cw, w);

        __half2 hacc[8];
#pragma unroll
        for (int i = 0; i < 8; i++) hacc[i] = __half2half2(__ushort_as_half(0));

#pragma unroll
        for (int b = 0; b < 4; b++) {
            int c = w * 4 + b;
            int code = (word >> (8 * b)) & 15;
            const uint4* row = (const uint4*)(Lh + ((size_t)(c * 16 + code) << 9));
#pragma unroll
            for (int J = 0; J < 2; J++) {
                uint4 v = row[lane + 32 * J];
                hacc[J * 4 + 0] = __hadd2(hacc[J * 4 + 0], *(__half2*)&v.x);
                hacc[J * 4 + 1] = __hadd2(hacc[J * 4 + 1], *(__half2*)&v.y);
                hacc[J * 4 + 2] = __hadd2(hacc[J * 4 + 2], *(__half2*)&v.z);
                hacc[J * 4 + 3] = __hadd2(hacc[J * 4 + 3], *(__half2*)&v.w);
            }
        }
#pragma unroll
        for (int J = 0; J < 2; J++)
#pragma unroll
            for (int p = 0; p < 4; p++) {
                float2 f = __half22float2(hacc[J * 4 + p]);
                acc[J * 8 + p * 2]     += f.x;
                acc[J * 8 + p * 2 + 1] += f.y;
            }
    }

    float4* op0 = (float4*)(out + (size_t)n * MDIM + lane * 8);
    op0[0] = make_float4(acc[0], acc[1], acc[2], acc[3]);
    op0[1] = make_float4(acc[4], acc[5], acc[6], acc[7]);
    float4* op1 = (float4*)(out + (size_t)n * MDIM + 256 + lane * 8);
    op1[0] = make_float4(acc[8], acc[9], acc[10], acc[11]);
    op1[1] = make_float4(acc[12], acc[13], acc[14], acc[15]);
}

// ---------------------------------------------------------------------------
extern "C" void kernel_launch(void* const* d_in, const int* in_sizes, int n_in,
                              void* d_out, int out_size)
{
    const float* I = (const float*)d_in[0];
    const float* A = (const float*)d_in[1];
    const float* T = (const float*)d_in[2];
    const float* L = (const float*)d_in[3];
    float* out = (float*)d_out;

    uint8_t* codes;
    __half* Lh;
    cudaGetSymbolAddress((void**)&codes, g_codes);
    cudaGetSymbolAddress((void**)&Lh, g_Lh);

    encode_kernel<<<NROWS / 8, 512>>>(I, A, T, codes);
    dim3 tgrid(MDIM / 32, 1024 / 32);
    convert_kernel<<<tgrid, 256>>>(L, Lh);
    decode_kernel<<<NROWS * 32 / 256, 256>>>(codes, Lh, out);
}

// round 17
// speedup vs baseline: 2.5682x; 1.1427x over previous
#include <cuda_runtime.h>
#include <cuda_fp16.h>
#include <cstdint>

#define NROWS 16384
#define CDIM  64
#define KDIM  16
#define DDIM  512
#define MDIM  512
#define NNODES 15

// ---------------------------------------------------------------------------
// scratch
// ---------------------------------------------------------------------------
__device__ uint8_t g_codes[NROWS * CDIM];        // 1 MB
__device__ __half  g_Lh[CDIM * KDIM * MDIM];     // 1 MB  [c][k][m] fp16, m contiguous

// ---------------------------------------------------------------------------
// tanh via e = exp2(2x*log2e):  t = (e-1)*rcp(e+1).  6 instrs, sign-free,
// abs err < ~3e-7. Score-gap error <= ~1.2e-6 over 4 terms.
// ---------------------------------------------------------------------------
__device__ __forceinline__ float tanh_e(float x) {
    float e;
    asm("ex2.approx.f32 %0, %1;" : "=f"(e) : "f"(x * 2.8853900817779268f));
    float r;
    asm("rcp.approx.f32 %0, %1;" : "=f"(r) : "f"(e + 1.0f));
    return (e - 1.0f) * r;
}

// partial-sum tree (30 adds) -> scores; argmax with runner-up.
__device__ __forceinline__ void leaf_scores(const float* t, float* s) {
    float p2[4], p3[8];
    p2[0] = -t[0] - t[1];  p2[1] = -t[0] + t[1];
    p2[2] =  t[0] - t[2];  p2[3] =  t[0] + t[2];
#pragma unroll
    for (int j = 0; j < 4; j++) {
        p3[2 * j]     = p2[j] - t[3 + j];
        p3[2 * j + 1] = p2[j] + t[3 + j];
    }
#pragma unroll
    for (int j = 0; j < 8; j++) {
        s[2 * j]     = p3[j] - t[7 + j];
        s[2 * j + 1] = p3[j] + t[7 + j];
    }
}

// ---------------------------------------------------------------------------
// Encode v6 = R16 lean pipeline + R15 safety semantics.
// LESSON (R16): ONE argmax flip = 1.4e-3 rel err = FAIL. Tolerance for flips
// is zero; the gap<1e-4 tanhf rung catches all candidates (score err 1.2e-6).
// ---------------------------------------------------------------------------
__global__ void __launch_bounds__(512) encode_kernel(
    const float* __restrict__ I, const float* __restrict__ A,
    const float* __restrict__ T, uint8_t* __restrict__ codes)
{
    __shared__ float4 sA4[8 * CDIM];    // (s, c) c-fastest: LDS.128 conflict-free
    __shared__ float4 sT4[4 * CDIM];    // (g, c): T[c][4g..4g+3], padded

    int tid = threadIdx.x;
    {   // A: 512 float4s, one per thread. src A4[c*8+s]
        const float4* A4 = (const float4*)A;
        sA4[(tid & 7) * CDIM + (tid >> 3)] = A4[tid];
    }
    for (int i = tid; i < CDIM * 16; i += 512) {   // T: padded scalar fill
        int c = i >> 4, j = i & 15;
        float v = (j < 15) ? T[c * NNODES + j] : 0.0f;
        ((float*)sT4)[(j >> 2) * (CDIM * 4) + c * 4 + (j & 3)] = v;
    }
    __syncthreads();

    const int c = tid & 63;
    const int n = blockIdx.x * 8 + (tid >> 6);

    const float4* Ip = (const float4*)(I + (size_t)n * DDIM + c * 8);
    float4 v0 = Ip[0], v1 = Ip[1];

    float x0 = 0.f, x1 = 0.f, x2 = 0.f, x3 = 0.f;
    {
        float iv[8] = {v0.x, v0.y, v0.z, v0.w, v1.x, v1.y, v1.z, v1.w};
#pragma unroll
        for (int s8 = 0; s8 < 8; s8++) {
            float4 a = sA4[s8 * CDIM + c];
            x0 = fmaf(iv[s8], a.x, x0);
            x1 = fmaf(iv[s8], a.y, x1);
            x2 = fmaf(iv[s8], a.z, x2);
            x3 = fmaf(iv[s8], a.w, x3);
        }
    }
    float x[4] = {x0, x1, x2, x3};

    float4 t4_0 = sT4[0 * CDIM + c];
    float4 t4_1 = sT4[1 * CDIM + c];
    float4 t4_2 = sT4[2 * CDIM + c];
    float4 t4_3 = sT4[3 * CDIM + c];
    float tc[NNODES] = {t4_0.x, t4_0.y, t4_0.z, t4_0.w,
                        t4_1.x, t4_1.y, t4_1.z, t4_1.w,
                        t4_2.x, t4_2.y, t4_2.z, t4_2.w,
                        t4_3.x, t4_3.y, t4_3.z};

    const int lvl[NNODES] = {0,1,1,2,2,2,2,3,3,3,3,3,3,3,3};
    float h[NNODES], t[NNODES];
#pragma unroll
    for (int i = 0; i < NNODES; i++) {
        h[i] = x[lvl[i]] - tc[i];
        t[i] = tanh_e(h[i]);
    }

    float s[16];
    leaf_scores(t, s);

    float best = -3.0e38f, second = -3.0e38f;
    int bestk = 0;
#pragma unroll
    for (int k = 0; k < KDIM; k++) {
        if (s[k] > best) { second = best; best = s[k]; bestk = k; }
        else if (s[k] > second) second = s[k];
    }

    if (best - second < 1e-4f) {     // rare (~1e-4 of items): exact tanhf redo
#pragma unroll
        for (int i = 0; i < NNODES; i++) t[i] = tanhf(h[i]);
        leaf_scores(t, s);
        best = s[0]; bestk = 0;
#pragma unroll
        for (int k = 1; k < KDIM; k++)
            if (s[k] > best) { best = s[k]; bestk = k; }
    }
    codes[(size_t)n * CDIM + c] = (uint8_t)bestk;
}

// ---------------------------------------------------------------------------
// Transpose+convert: L [m][ck] f32 -> Lh [ck][m] fp16, smem-tiled 32x32
// ---------------------------------------------------------------------------
__global__ void __launch_bounds__(256) convert_kernel(
    const float* __restrict__ L, __half* __restrict__ Lh)
{
    __shared__ __half st[32][33];
    const int m0  = blockIdx.x * 32;
    const int ck0 = blockIdx.y * 32;
    const int tx = threadIdx.x & 31, ty8 = threadIdx.x >> 5;   // 32 x 8
#pragma unroll
    for (int r = 0; r < 4; r++) {
        int m = m0 + ty8 + r * 8;
        st[tx][ty8 + r * 8] = __float2half(L[(size_t)m * 1024 + ck0 + tx]);
    }
    __syncthreads();
#pragma unroll
    for (int r = 0; r < 4; r++) {
        int ck = ck0 + ty8 + r * 8;
        Lh[(size_t)ck * MDIM + m0 + tx] = st[ty8 + r * 8][tx];
    }
}

// ---------------------------------------------------------------------------
// Decode (unchanged): one warp per n; warp-uniform codes; LDG.128 dense
// fp16 rows; HADD2 group accumulation (4 c's), fp32 flush.
// ---------------------------------------------------------------------------
__global__ void __launch_bounds__(256) decode_kernel(
    const uint8_t* __restrict__ codes,
    const __half* __restrict__ Lh,
    float* __restrict__ out)
{
    const int n    = (blockIdx.x * 256 + threadIdx.x) >> 5;
    const int lane = threadIdx.x & 31;

    const uint32_t* cwp = (const uint32_t*)(codes + (size_t)n * CDIM);
    uint32_t cw = (lane < 16) ? cwp[lane] : 0;

    float acc[16];
#pragma unroll
    for (int i = 0; i < 16; i++) acc[i] = 0.0f;

#pragma unroll 4
    for (int w = 0; w < 16; w++) {
        uint32_t word = __shfl_sync(0xffffffffu, cw, w);

        __half2 hacc[8];
#pragma unroll
        for (int i = 0; i < 8; i++) hacc[i] = __half2half2(__ushort_as_half(0));

#pragma unroll
        for (int b = 0; b < 4; b++) {
            int c = w * 4 + b;
            int code = (word >> (8 * b)) & 15;
            const uint4* row = (const uint4*)(Lh + ((size_t)(c * 16 + code) << 9));
#pragma unroll
            for (int J = 0; J < 2; J++) {
                uint4 v = row[lane + 32 * J];
                hacc[J * 4 + 0] = __hadd2(hacc[J * 4 + 0], *(__half2*)&v.x);
                hacc[J * 4 + 1] = __hadd2(hacc[J * 4 + 1], *(__half2*)&v.y);
                hacc[J * 4 + 2] = __hadd2(hacc[J * 4 + 2], *(__half2*)&v.z);
                hacc[J * 4 + 3] = __hadd2(hacc[J * 4 + 3], *(__half2*)&v.w);
            }
        }
#pragma unroll
        for (int J = 0; J < 2; J++)
#pragma unroll
            for (int p = 0; p < 4; p++) {
                float2 f = __half22float2(hacc[J * 4 + p]);
                acc[J * 8 + p * 2]     += f.x;
                acc[J * 8 + p * 2 + 1] += f.y;
            }
    }

    float4* op0 = (float4*)(out + (size_t)n * MDIM + lane * 8);
    op0[0] = make_float4(acc[0], acc[1], acc[2], acc[3]);
    op0[1] = make_float4(acc[4], acc[5], acc[6], acc[7]);
    float4* op1 = (float4*)(out + (size_t)n * MDIM + 256 + lane * 8);
    op1[0] = make_float4(acc[8], acc[9], acc[10], acc[11]);
    op1[1] = make_float4(acc[12], acc[13], acc[14], acc[15]);
}

// ---------------------------------------------------------------------------
extern "C" void kernel_launch(void* const* d_in, const int* in_sizes, int n_in,
                              void* d_out, int out_size)
{
    const float* I = (const float*)d_in[0];
    const float* A = (const float*)d_in[1];
    const float* T = (const float*)d_in[2];
    const float* L = (const float*)d_in[3];
    float* out = (float*)d_out;

    uint8_t* codes;
    __half* Lh;
    cudaGetSymbolAddress((void**)&codes, g_codes);
    cudaGetSymbolAddress((void**)&Lh, g_Lh);

    encode_kernel<<<NROWS / 8, 512>>>(I, A, T, codes);
    dim3 tgrid(MDIM / 32, 1024 / 32);
    convert_kernel<<<tgrid, 256>>>(L, Lh);
    decode_kernel<<<NROWS * 32 / 256, 256>>>(codes, Lh, out);
}